// round 7
// baseline (speedup 1.0000x reference)
#include <cuda_runtime.h>
#include <math.h>

#define BB 2
#define NN 2048
#define CC 256
#define HH 8
#define DHH 32
#define SCALE 0.17677669529663687f  // 1/sqrt(32)
#define CH 256                       // scan chunk size (NN/8)

typedef unsigned long long u64;

// ---- scratch ----
__device__ float g_qT[BB*HH*DHH*NN];   // [bh][d][n], pre-scaled
__device__ float g_kT[BB*HH*DHH*NN];   // [bh][d][n]
__device__ float g_v [BB*HH*NN*DHH];   // [bh][n][d]
__device__ float g_ctx[BB*NN*CC];
__device__ float g_pm[HH*NN];
__device__ float g_pinv[HH*NN];
__device__ float g_scanF[BB*HH*NN*DHH];  // fwd scan, then pos numerator (in-place)
__device__ float g_scanG[BB*HH*NN*DHH];  // bwd scan

// ---- f32x2 helpers ----
__device__ __forceinline__ void fma2(u64 &acc, u64 a, u64 b) {
    asm("fma.rn.f32x2 %0, %1, %2, %0;" : "+l"(acc) : "l"(a), "l"(b));
}
__device__ __forceinline__ u64 dup2(float x) {
    u64 r; asm("mov.b64 %0, {%1, %1};" : "=l"(r) : "f"(x)); return r;
}
__device__ __forceinline__ float2 unpack2(u64 v) {
    float2 r; asm("mov.b64 {%0, %1}, %2;" : "=f"(r.x), "=f"(r.y) : "l"(v)); return r;
}

// ============================================================
// 1) pos softmax row stats, closed form (geometric series).
//    pm_i = b + max(0, a+*i, a-*(N-1-i)); pinv_i = 1/den_i.
// ============================================================
__global__ void pos_stats_kernel(const float* __restrict__ Wpos,
                                 const float* __restrict__ bpos) {
    int idx = blockIdx.x * blockDim.x + threadIdx.x;
    if (idx >= HH * NN) return;
    int h = idx / NN, i = idx - h * NN;
    float W0 = Wpos[h], W1 = Wpos[HH + h], bph = bpos[h];
    float apos = W0 + W1;           // slope for d>0
    float aneg = W1 - W0;           // slope for d<0
    float fi = (float)i, fM = (float)(NN - 1 - i);
    float mi = fmaxf(0.f, fmaxf(apos * fi, aneg * fM));

    float Sp;
    if (i == 0)            Sp = 0.f;
    else if (apos > 0.f)   Sp = __expf(apos * fi - mi) * expm1f(-apos * fi) / expm1f(-apos);
    else if (apos < 0.f)   Sp = __expf(apos - mi) * expm1f(apos * fi) / expm1f(apos);
    else                   Sp = fi * __expf(-mi);

    float Sn;
    if (i == NN - 1)       Sn = 0.f;
    else if (aneg > 0.f)   Sn = __expf(aneg * fM - mi) * expm1f(-aneg * fM) / expm1f(-aneg);
    else if (aneg < 0.f)   Sn = __expf(aneg - mi) * expm1f(aneg * fM) / expm1f(aneg);
    else                   Sn = fM * __expf(-mi);

    float den = __expf(-mi) + Sp + Sn;
    g_pm[idx]   = bph + mi;
    g_pinv[idx] = 1.f / den;
}

// ============================================================
// 2) QKV GEMM -> g_qT (scaled), g_kT, g_v
// ============================================================
__global__ void qkv_gemm_kernel(const float* __restrict__ x,
                                const float* __restrict__ Wqk,
                                const float* __restrict__ Wv) {
    __shared__ float As[16][64];
    __shared__ float Bs[16][64];
    int tid = threadIdx.x;
    int ty = tid >> 4, tx = tid & 15;
    int m0 = blockIdx.x * 64, n0 = blockIdx.y * 64;
    float acc[4][4] = {};
    int arow = tid >> 2, acol = (tid & 3) * 4;
    int brow = tid >> 4, bcol = (tid & 15) * 4;

    for (int k0 = 0; k0 < 256; k0 += 16) {
        float4 av = *(const float4*)&x[(m0 + arow) * 256 + k0 + acol];
        As[acol + 0][arow] = av.x; As[acol + 1][arow] = av.y;
        As[acol + 2][arow] = av.z; As[acol + 3][arow] = av.w;
        int gc = n0 + bcol;
        float4 bv;
        if (gc < 512) bv = *(const float4*)&Wqk[(k0 + brow) * 512 + gc];
        else          bv = *(const float4*)&Wv[(k0 + brow) * 256 + gc - 512];
        *(float4*)&Bs[brow][bcol] = bv;
        __syncthreads();
        #pragma unroll
        for (int kk = 0; kk < 16; kk++) {
            float4 a = *(float4*)&As[kk][4 * ty];
            float4 b = *(float4*)&Bs[kk][4 * tx];
            float aa[4] = {a.x, a.y, a.z, a.w};
            float bb[4] = {b.x, b.y, b.z, b.w};
            #pragma unroll
            for (int i = 0; i < 4; i++)
                #pragma unroll
                for (int j = 0; j < 4; j++)
                    acc[i][j] += aa[i] * bb[j];
        }
        __syncthreads();
    }
    #pragma unroll
    for (int i = 0; i < 4; i++) {
        int m = m0 + 4 * ty + i;
        int b = m >> 11, n = m & (NN - 1);
        #pragma unroll
        for (int j = 0; j < 4; j++) {
            int c = n0 + 4 * tx + j;
            float v = acc[i][j];
            if (c < 256) {
                int h = c >> 5, d = c & 31;
                g_qT[((b * HH + h) * DHH + d) * NN + n] = v * SCALE;
            } else if (c < 512) {
                int cc = c - 256; int h = cc >> 5, d = cc & 31;
                g_kT[((b * HH + h) * DHH + d) * NN + n] = v;
            } else {
                int cc = c - 512; int h = cc >> 5, d = cc & 31;
                g_v[((b * HH + h) * NN + n) * DHH + d] = v;
            }
        }
    }
}

// ============================================================
// 3) POS path: blocked-parallel exponential scans, O(N*Dh)/head.
//    One block per (b,h): 8 warps x 256-row chunks.
//    Phase1: local fwd+bwd scans.  Phase2: 8-step carry scans.
//    Phase3: apply carries + row coeffs -> pos numerator in g_scanF.
// ============================================================
__global__ void __launch_bounds__(256) pos_scan_kernel(const float* __restrict__ Wpos,
                                                       const float* __restrict__ bpos) {
    __shared__ float TFs[8][32], TGs[8][32], AFs[8][32], DGs[8][32];

    int bh = blockIdx.x;
    int h = bh & (HH - 1);
    int tid = threadIdx.x;
    int w = tid >> 5, lane = tid & 31;
    float apos = Wpos[h] + Wpos[HH + h];
    float aneg = Wpos[HH + h] - Wpos[h];
    bool posg = apos > 0.f, negg = aneg > 0.f;
    float rhoF = posg ? 1.f : __expf(apos);
    float rhoG = negg ? 1.f : __expf(aneg);
    float wcF = posg ? -apos : 0.f;           // fwd basis exponent coeff
    float wcG = negg ? -aneg : 0.f;           // bwd basis exponent coeff
    float usG = negg ? 1.f : rhoG;            // bwd u scale

    const float* vp = g_v + bh * NN * DHH + lane;
    float* fo = g_scanF + bh * NN * DHH + lane;
    float* go = g_scanG + bh * NN * DHH + lane;
    int c0 = w * CH;

    // ---- phase 1: local scans ----
    float F = 0.f;
    for (int ib = c0; ib < c0 + CH; ib += 8) {
        float vb[8];
        #pragma unroll
        for (int u = 0; u < 8; u++) vb[u] = vp[(ib + u) * DHH];
        #pragma unroll
        for (int u = 0; u < 8; u++) {
            float uu = vb[u] * __expf(wcF * (float)(ib + u));
            F = rhoF * F + uu;
            fo[(ib + u) * DHH] = F;
        }
    }
    TFs[w][lane] = F;

    float G = 0.f;
    for (int ib = c0 + CH - 1; ib >= c0; ib -= 8) {
        float vb[8];
        #pragma unroll
        for (int u = 0; u < 8; u++) vb[u] = vp[(ib - u) * DHH];
        #pragma unroll
        for (int u = 0; u < 8; u++) {
            int i = ib - u;
            go[i * DHH] = G;
            float uu = usG * vb[u] * __expf(wcG * (float)(NN - 1 - i));
            G = rhoG * G + uu;
        }
    }
    TGs[w][lane] = G;
    __syncthreads();

    // ---- phase 2: carry scans over 8 chunks (per lane) ----
    if (w == 0) {
        float fF = posg ? 1.f : __expf(apos * (float)CH);
        float A = 0.f;
        #pragma unroll
        for (int c = 0; c < 8; c++) { AFs[c][lane] = A; A = TFs[c][lane] + fF * A; }
    } else if (w == 1) {
        float fG = negg ? 1.f : __expf(aneg * (float)CH);
        float D = 0.f;
        #pragma unroll
        for (int c = 7; c >= 0; c--) { DGs[c][lane] = D; D = TGs[c][lane] + fG * D; }
    }
    __syncthreads();

    // ---- phase 3: apply carries + per-row coeffs -> pnum ----
    float A = AFs[w][lane];
    float D = DGs[w][lane];
    float pfc = posg ? 0.f : apos;   // carry factor coeff fwd
    float gfc = negg ? 0.f : aneg;   // carry factor coeff bwd
    float bph = bpos[h];
    float pp = fmaxf(apos, 0.f), pn = fmaxf(aneg, 0.f);
    const float* pmrow = g_pm + h * NN;
    int cend = c0 + CH;
    for (int i = c0; i < cend; i++) {
        float Fg = fo[i * DHH] + A * __expf(pfc * (float)(i - c0 + 1));
        float Gg = go[i * DHH] + D * __expf(gfc * (float)(cend - 1 - i));
        float pm = pmrow[i];
        float c1 = __expf(bph + pp * (float)i - pm);
        float c2 = __expf(bph + pn * (float)(NN - 1 - i) - pm);
        fo[i * DHH] = c1 * Fg + c2 * Gg;
    }
}

// ============================================================
// helper: load a [32][128] transposed tile into smem pad-132
// ============================================================
__device__ __forceinline__ void load_tile_T132(float (*dst)[132],
                                               const float* __restrict__ src,
                                               int n0, int tid) {
    #pragma unroll
    for (int r = 0; r < 4; r++) {
        int idx = tid + r * 256;
        int c  = idx & 15;
        int d  = (idx >> 4) & 31;
        int h2 = idx >> 9;
        int col = 4 * (c + 16 * h2);
        float4 v = *(const float4*)&src[d * NN + n0 + col];
        *(float4*)&dst[d][col] = v;
    }
}

// ============================================================
// 4) PATCH attention: QK + exp + l + PV; epilogue adds pos numerator.
// ============================================================
__global__ void __launch_bounds__(256, 2) attn_patch_kernel(const float* __restrict__ gating) {
    __shared__ float qs[32][132];    // [d][q]
    __shared__ float ksd[32][68];    // [d][2*k] duplicated pairs
    __shared__ float vs[32][36];     // [k][d]
    __shared__ float pT[32][132];    // [k][q]

    int tid = threadIdx.x;
    int ty = tid >> 4, tx = tid & 15;
    int qt = blockIdx.x, h = blockIdx.y, b = blockIdx.z;
    int bh = b * HH + h;
    int q0 = qt * 128;
    const float* qg = g_qT + bh * DHH * NN;
    const float* kg = g_kT + bh * DHH * NN;
    const float* vg = g_v  + bh * NN * DHH;

    load_tile_T132(qs, qg, q0, tid);

    int dx = tid & 7, ks2 = (tid >> 3) & 1;
    u64 oaccP[4][4] = {};
    float l[8] = {};

    for (int kt = 0; kt < 64; kt++) {
        int k0 = kt * 32;
        __syncthreads();
        {   // loads: ksd (duplicated), vs
            int d = tid >> 3, c = tid & 7;
            float4 kv = *(const float4*)&kg[d * NN + k0 + 4 * c];
            *(float4*)&ksd[d][8 * c]     = make_float4(kv.x, kv.x, kv.y, kv.y);
            *(float4*)&ksd[d][8 * c + 4] = make_float4(kv.z, kv.z, kv.w, kv.w);
            *(float4*)&vs[d][4 * c] = *(const float4*)&vg[(k0 + d) * DHH + 4 * c];
        }
        __syncthreads();

        // ---- QK: 8q x 2k per thread ----
        u64 sacc[4][2] = {};
        #pragma unroll
        for (int d = 0; d < 32; d++) {
            ulonglong2 a0 = *(const ulonglong2*)&qs[d][8 * ty];
            ulonglong2 a1 = *(const ulonglong2*)&qs[d][8 * ty + 4];
            u64 ap[4] = {a0.x, a0.y, a1.x, a1.y};
            u64 bd0 = *(const u64*)&ksd[d][2 * tx];
            u64 bd1 = *(const u64*)&ksd[d][2 * tx + 32];
            #pragma unroll
            for (int p = 0; p < 4; p++) {
                fma2(sacc[p][0], ap[p], bd0);
                fma2(sacc[p][1], ap[p], bd1);
            }
        }
        // ---- patch weights -> pT, accumulate l ----
        #pragma unroll
        for (int p = 0; p < 4; p++) {
            int i0 = 8 * ty + 2 * p;
            #pragma unroll
            for (int j = 0; j < 2; j++) {
                int kc = tx + 16 * j;
                float2 s = unpack2(sacc[p][j]);
                float e0 = __expf(s.x), e1 = __expf(s.y);
                pT[kc][i0] = e0; pT[kc][i0 + 1] = e1;
                l[2*p] += e0; l[2*p+1] += e1;
            }
        }
        __syncthreads();
        // ---- PV (2-way split over k within tile) ----
        #pragma unroll
        for (int kk = 0; kk < 16; kk++) {
            int k = 2 * kk + ks2;
            ulonglong2 a0 = *(const ulonglong2*)&pT[k][8 * ty];
            ulonglong2 a1 = *(const ulonglong2*)&pT[k][8 * ty + 4];
            u64 ap[4] = {a0.x, a0.y, a1.x, a1.y};
            float4 bv = *(const float4*)&vs[k][4 * dx];
            u64 bd[4] = {dup2(bv.x), dup2(bv.y), dup2(bv.z), dup2(bv.w)};
            #pragma unroll
            for (int p = 0; p < 4; p++)
                #pragma unroll
                for (int j = 0; j < 4; j++)
                    fma2(oaccP[p][j], ap[p], bd[j]);
        }
    }

    // ---- reduce l across 16 tx lanes ----
    #pragma unroll
    for (int o = 8; o; o >>= 1)
        #pragma unroll
        for (int r = 0; r < 8; r++)
            l[r] += __shfl_xor_sync(0xffffffffu, l[r], o);

    float gv = 1.f / (1.f + __expf(-gating[h]));
    float s1[8], s2[8];
    #pragma unroll
    for (int r = 0; r < 8; r++) {
        int row = q0 + 8 * ty + r;
        s1[r] = (1.f - gv) / l[r];
        s2[r] = gv * g_pinv[h * NN + row];
    }
    // ---- combine with pos numerator, split-k reduce, store ----
    #pragma unroll
    for (int p = 0; p < 4; p++) {
        float o0a[4], o1a[4];
        #pragma unroll
        for (int j = 0; j < 4; j++) {
            float2 vp = unpack2(oaccP[p][j]);
            float o0 = s1[2*p]   * vp.x;
            float o1 = s1[2*p+1] * vp.y;
            o0 += __shfl_xor_sync(0xffffffffu, o0, 8);
            o1 += __shfl_xor_sync(0xffffffffu, o1, 8);
            o0a[j] = o0; o1a[j] = o1;
        }
        if (tx < 8) {
            int row = q0 + 8 * ty + 2 * p;
            const float* pnp = &g_scanF[(bh * NN + row) * DHH + 4 * tx];
            float4 p0 = *(const float4*)pnp;
            float4 p1 = *(const float4*)(pnp + DHH);
            float a2 = s2[2*p], b2 = s2[2*p+1];
            float4 r0 = make_float4(o0a[0] + a2*p0.x, o0a[1] + a2*p0.y,
                                    o0a[2] + a2*p0.z, o0a[3] + a2*p0.w);
            float4 r1 = make_float4(o1a[0] + b2*p1.x, o1a[1] + b2*p1.y,
                                    o1a[2] + b2*p1.z, o1a[3] + b2*p1.w);
            int col = h * 32 + 4 * tx;
            *(float4*)&g_ctx[(b * NN + row) * CC + col]     = r0;
            *(float4*)&g_ctx[(b * NN + row + 1) * CC + col] = r1;
        }
    }
}

// ============================================================
// 5) Output projection
// ============================================================
__global__ void proj_gemm_kernel(const float* __restrict__ Wp,
                                 const float* __restrict__ bp,
                                 float* __restrict__ out) {
    __shared__ float As[16][64];
    __shared__ float Bs[16][64];
    int tid = threadIdx.x;
    int ty = tid >> 4, tx = tid & 15;
    int m0 = blockIdx.x * 64, n0 = blockIdx.y * 64;
    float acc[4][4] = {};
    int arow = tid >> 2, acol = (tid & 3) * 4;
    int brow = tid >> 4, bcol = (tid & 15) * 4;

    for (int k0 = 0; k0 < 256; k0 += 16) {
        float4 av = *(const float4*)&g_ctx[(m0 + arow) * 256 + k0 + acol];
        As[acol + 0][arow] = av.x; As[acol + 1][arow] = av.y;
        As[acol + 2][arow] = av.z; As[acol + 3][arow] = av.w;
        float4 bv = *(const float4*)&Wp[(k0 + brow) * 256 + n0 + bcol];
        *(float4*)&Bs[brow][bcol] = bv;
        __syncthreads();
        #pragma unroll
        for (int kk = 0; kk < 16; kk++) {
            float4 a = *(float4*)&As[kk][4 * ty];
            float4 b = *(float4*)&Bs[kk][4 * tx];
            float aa[4] = {a.x, a.y, a.z, a.w};
            float bb[4] = {b.x, b.y, b.z, b.w};
            #pragma unroll
            for (int i = 0; i < 4; i++)
                #pragma unroll
                for (int j = 0; j < 4; j++)
                    acc[i][j] += aa[i] * bb[j];
        }
        __syncthreads();
    }
    #pragma unroll
    for (int i = 0; i < 4; i++) {
        int m = m0 + 4 * ty + i;
        #pragma unroll
        for (int j = 0; j < 4; j++) {
            int c = n0 + 4 * tx + j;
            out[m * 256 + c] = acc[i][j] + bp[c];
        }
    }
}

// ============================================================
extern "C" void kernel_launch(void* const* d_in, const int* in_sizes, int n_in,
                              void* d_out, int out_size) {
    const float* x     = (const float*)d_in[0];
    const float* Wqk   = (const float*)d_in[1];
    const float* Wv    = (const float*)d_in[2];
    const float* Wproj = (const float*)d_in[3];
    const float* bproj = (const float*)d_in[4];
    const float* Wpos  = (const float*)d_in[5];
    const float* bpos  = (const float*)d_in[6];
    const float* gate  = (const float*)d_in[7];
    float* out = (float*)d_out;

    pos_stats_kernel<<<(HH * NN + 255) / 256, 256>>>(Wpos, bpos);
    qkv_gemm_kernel<<<dim3(BB * NN / 64, 12), 256>>>(x, Wqk, Wv);
    pos_scan_kernel<<<BB * HH, 256>>>(Wpos, bpos);
    attn_patch_kernel<<<dim3(NN / 128, HH, BB), 256>>>(gate);
    proj_gemm_kernel<<<dim3(BB * NN / 64, 4), 256>>>(Wproj, bproj, out);
}